// round 12
// baseline (speedup 1.0000x reference)
#include <cuda_runtime.h>

#define BB 64
#define CC 3
#define RR 64
#define CL 64
#define EE 64
#define HH 32
#define LL 3
#define VV 258
#define GG 96   // 3*H

typedef unsigned long long u64;

// ---------------- scratch (device globals; no allocation) ----------------
__device__ float g_giemb[CC * VV * GG];                   // [c][v][g] = Wih0[:, :64] @ embed
__device__ float g_wpk[CC * 576 * 48];                    // per-thread packed half-rows: wi[16], wh[16], wq[16]
__device__ float g_bpk[CC * 576 * 4];                     // per-thread bias: (bi, bh, pv, 0)
__device__ float g_hid[(size_t)BB * CC * RR * CL * HH];   // all hidden outputs (~100 MB)

// ---------------- helpers ----------------
#define FMA2(acc, a, b) asm("fma.rn.f32x2 %0, %1, %2, %0;" : "+l"(acc) : "l"(a), "l"(b))

__device__ __forceinline__ float sum2p(u64 a, u64 b) {
    u64 s;
    asm("add.rn.f32x2 %0, %1, %2;" : "=l"(s) : "l"(a), "l"(b));
    float lo = __uint_as_float((unsigned)(s & 0xffffffffull));
    float hi = __uint_as_float((unsigned)(s >> 32));
    return lo + hi;
}
__device__ __forceinline__ void cpa16(void* dst, const void* src) {
    unsigned sd = (unsigned)__cvta_generic_to_shared(dst);
    asm volatile("cp.async.ca.shared.global [%0], [%1], 16;" :: "r"(sd), "l"(src) : "memory");
}
__device__ __forceinline__ float sigm_a(float x) {
    float t;
    asm("tanh.approx.f32 %0, %1;" : "=f"(t) : "f"(0.5f * x));
    return fmaf(0.5f, t, 0.5f);
}
__device__ __forceinline__ float tanh_a(float x) {
    float t;
    asm("tanh.approx.f32 %0, %1;" : "=f"(t) : "f"(x));
    return t;
}

// thread -> (layer, gate, half) mapping (R9, validated):
//   l = tid/192; r192 = tid%192; w6 = r192/32; lane = r192%32;
//   g = 16*w6 + (lane & 15); hf = lane >> 4.
// Halves of one gate sit in lanes k and k^16 of the same warp (shfl_xor 16 combine).
// Warps 0-3 of a group hold r,z gates (g<64); warps 4-5 hold n gates (uniform branches).

// ---------------- dynamic shared layout ----------------
struct SmemT {
    float hs0[RR][HH];       // layer-0 hidden per row
    float hs1[RR][HH];       // layer-1 hidden per row
    float hs2[RR + 1][HH];   // layer-2 hidden per row, +1 offset; [0] = zeros (row -1)
    float rz[LL][32][64];    // finished sigma(r), sigma(z) per (layer, slot=r&31)
    float2 n2[LL][32][HH];   // (i_n, h_n) pairs
    float pout[2][32][HH];   // prev-channel outputs, double-buffered by step parity
    int xs[RR * CL];         // whole channel's x indices
};

// ---------------- precompute kernels (R9 576-thread layouts, proven) ----------------
__global__ void prep_giemb(const float* __restrict__ Wih0, const float* __restrict__ embed) {
    int idx = blockIdx.x * blockDim.x + threadIdx.x;
    if (idx >= CC * VV * GG) return;
    int c = idx / (VV * GG);
    int rem = idx % (VV * GG);
    int v = rem / GG;
    int g = rem % GG;
    const float* wr = Wih0 + (c * GG + g) * (EE + 1);
    const float* em = embed + (c * VV + v) * EE;
    float acc = 0.f;
#pragma unroll
    for (int e = 0; e < EE; e++) acc += wr[e] * em[e];
    g_giemb[idx] = acc;
}

__global__ void prep_wpk3(const float* __restrict__ Wih0, const float* __restrict__ Wih_rest,
                          const float* __restrict__ Whh, const float* __restrict__ W_h2e,
                          const float* __restrict__ W_ad) {
    int idx = blockIdx.x * blockDim.x + threadIdx.x;
    if (idx >= CC * 576 * 48) return;
    int c = idx / (576 * 48);
    int rem = idx % (576 * 48);
    int t = rem / 48;
    int j = rem % 48;
    int side = j / 16, q = j % 16;
    int l = t / 192;
    int r192 = t % 192;
    int w6 = r192 >> 5, lane = r192 & 31;
    int g = (w6 << 4) | (lane & 15);
    int hf = lane >> 4;
    int e = hf * 16 + q;  // element within the 32-wide hidden vector
    float val = 0.f;
    if (side == 0) {
        if (l == 0) {
            const float* wr = Wih0 + (c * GG + g) * (EE + 1);
            for (int ee = 0; ee <= EE; ee++)
                val += wr[ee] * W_h2e[(c * (EE + 1) + ee) * HH + e];
        } else {
            val = Wih_rest[((c * (LL - 1) + (l - 1)) * GG + g) * HH + e];
        }
    } else if (side == 1) {
        val = Whh[((c * LL + l) * GG + g) * HH + e];
    } else {
        if (l == 0 && c > 0) {
            const float* wr = Wih0 + (c * GG + g) * (EE + 1);
            for (int ee = 0; ee <= EE; ee++)
                val += wr[ee] * W_ad[((c - 1) * (EE + 1) + ee) * HH + e];
        }
    }
    g_wpk[idx] = val;
}

__global__ void prep_bpk3(const float* __restrict__ Wih0, const float* __restrict__ bih,
                          const float* __restrict__ bhh, const float* __restrict__ b_h2e,
                          const float* __restrict__ b_ad) {
    int idx = blockIdx.x * blockDim.x + threadIdx.x;
    if (idx >= CC * 576) return;
    int c = idx / 576;
    int t = idx % 576;
    int l = t / 192;
    int r192 = t % 192;
    int w6 = r192 >> 5, lane = r192 & 31;
    int g = (w6 << 4) | (lane & 15);
    float bi, bh, pv;
    if (l == 0) {
        bi = bih[(c * LL + 0) * GG + g];
        const float* wr = Wih0 + (c * GG + g) * (EE + 1);
        for (int e = 0; e <= EE; e++) {
            float bb = b_h2e[c * (EE + 1) + e];
            if (c > 0) bb += b_ad[(c - 1) * (EE + 1) + e];
            bi += wr[e] * bb;
        }
        pv = Wih0[(c * GG + g) * (EE + 1) + EE];
    } else {
        bi = bih[(c * LL + l) * GG + g];
        pv = 0.f;
    }
    bh = bhh[(c * LL + l) * GG + g];
    g_bpk[idx * 4 + 0] = bi;
    g_bpk[idx * 4 + 1] = bh;
    g_bpk[idx * 4 + 2] = pv;
    g_bpk[idx * 4 + 3] = 0.f;
}

// ---------------- wavefront RNN kernel, 576 threads ----------------
// Schedule: layer l of cell (r,t) runs at step s = 3r + t + l (all deps one step old).
// Gate phase: thread (l, w6, lane) computes half hf of gate g over the <=22 diagonal
// cells; halves combined by shfl_xor(16); hf==0 applies activation and stores.
// Cell phase: 6 cells in flight (cell = rlo + w6 + 6k, unit = lane).
// cp.async protocol (R11, proven): issue(s+2) -> commit -> wait_group 1 -> bar.
__global__ void __launch_bounds__(576, 1) rnn_kernel(const int* __restrict__ x) {
    extern __shared__ __align__(16) char smem_raw[];
    SmemT* sm = reinterpret_cast<SmemT*>(smem_raw);

    const int b = blockIdx.x;
    const int tid = threadIdx.x;
    const int l = tid / 192;            // layer group (warp-uniform)
    const int r192 = tid % 192;
    const int w6 = r192 >> 5;           // warp within group
    const int lane = r192 & 31;
    const int g = (w6 << 4) | (lane & 15);  // gate 0..95
    const int hf = lane >> 4;           // half 0/1 of the dot
    const bool isRZ = (w6 < 4);         // warp-uniform gate type

    for (int c = 0; c < CC; c++) {
        // per-thread packed half-rows (f32x2 pairs): depth-2 chains per accumulator
        const ulonglong2* wv =
            reinterpret_cast<const ulonglong2*>(g_wpk + ((size_t)(c * 576 + tid)) * 48);
        ulonglong2 wi[4], wh[4], wq[4];
#pragma unroll
        for (int i = 0; i < 4; i++) wi[i] = wv[i];
#pragma unroll
        for (int i = 0; i < 4; i++) wh[i] = wv[4 + i];
#pragma unroll
        for (int i = 0; i < 4; i++) wq[i] = wv[8 + i];
        const float4 bias = reinterpret_cast<const float4*>(g_bpk)[c * 576 + tid];

        const float* giC = g_giemb + (size_t)c * VV * GG;
        const float* poutG = g_hid + (size_t)(b * CC + (c > 0 ? c - 1 : 0)) * (RR * CL * HH);
        float* hidG = g_hid + (size_t)(b * CC + c) * (RR * CL * HH);
        const int* xc = x + (size_t)(b * CC + c) * (RR * CL);

        // zero hidden states (hs0,hs1,hs2 contiguous)
        for (int i = tid; i < (RR + RR + RR + 1) * HH; i += 576) (&sm->hs0[0][0])[i] = 0.f;

        // pout prefetch: fill buf (m2&1) with pout for layer-0 cells on line 3r+t = m2
        auto issue_pout = [&](int m2) {
            if (c == 0 || m2 > 252) return;
            int rlo = m2 > 61 ? (m2 - 61) / 3 : 0;
            int rhi = min(63, m2 / 3);
            int nch = (rhi - rlo + 1) << 3;
            if (l == 0) {
                for (int id = r192; id < nch; id += 192) {
                    int ce = id >> 3, sub = id & 7;
                    int r = rlo + ce, t = m2 - 3 * r;
                    cpa16(&sm->pout[m2 & 1][r & 31][sub * 4],
                          poutG + ((size_t)(r * CL + t) * HH + sub * 4));
                }
            }
        };

        // prologue: whole-channel x + pout(0); then pout(1); publish before the loop
        for (int i = tid; i < (RR * CL) / 4; i += 576)
            cpa16((char*)&sm->xs[0] + i * 16, (const char*)xc + i * 16);
        issue_pout(0);
        asm volatile("cp.async.commit_group;" ::: "memory");
        issue_pout(1);
        asm volatile("cp.async.commit_group;" ::: "memory");
        asm volatile("cp.async.wait_group 1;" ::: "memory");  // xs + pout(0) landed
        __syncthreads();                                       // ... published to all threads

        for (int s = 0; s < 255; s++) {
            const int m = s - l;  // warp-uniform diagonal for this layer group
            const bool act = (m >= 0) && (m <= 252);
            int rlo = 0, rhi = -1;
            if (act) {
                rlo = m > 61 ? (m - 61) / 3 : 0;
                rhi = min(63, m / 3);
            }

            // ---------- gate phase ----------
            if (act) {
                if (l == 0) {
                    int p = rlo * CL + (m - 3 * rlo);
                    float qv = (hf == 0) ? __ldg(giC + (size_t)sm->xs[p] * GG + g) : 0.f;
                    for (int r = rlo; r <= rhi; r++) {
                        float qn = 0.f;
                        if (hf == 0 && r < rhi)
                            qn = __ldg(giC + (size_t)sm->xs[p + 61] * GG + g);
                        u64 A0 = 0, A1 = 0, B0 = 0, B1 = 0;
                        const ulonglong2* hv =
                            reinterpret_cast<const ulonglong2*>(&sm->hs0[r][0] + (hf << 4));
                        const ulonglong2* iv =
                            reinterpret_cast<const ulonglong2*>(&sm->hs2[r][0] + (hf << 4));
                        const ulonglong2* pv =
                            reinterpret_cast<const ulonglong2*>(&sm->pout[s & 1][r & 31][0] + (hf << 4));
#pragma unroll
                        for (int i = 0; i < 4; i++) {
                            FMA2(A0, wh[i].x, hv[i].x);
                            FMA2(A1, wh[i].y, hv[i].y);
                            FMA2(B0, wi[i].x, iv[i].x);
                            FMA2(B1, wi[i].y, iv[i].y);
                        }
                        if (c > 0) {
#pragma unroll
                            for (int i = 0; i < 4; i++) {
                                FMA2(B0, wq[i].x, pv[i].x);
                                FMA2(B1, wq[i].y, pv[i].y);
                            }
                        }
                        float ph = sum2p(A0, A1);
                        float pi = sum2p(B0, B1);
                        pi += __shfl_xor_sync(0xffffffffu, pi, 16);
                        ph += __shfl_xor_sync(0xffffffffu, ph, 16);
                        if (hf == 0) {
                            float ah = ph + bias.y;
                            float pos = (float)r * (1.f / 32.f) - 1.f;
                            float ai = pi + qv + fmaf(bias.z, pos, bias.x);
                            int slot = r & 31;
                            if (isRZ) sm->rz[0][slot][g] = sigm_a(ai + ah);
                            else sm->n2[0][slot][g - 64] = make_float2(ai, ah);
                        }
                        qv = qn;
                        p += 61;
                    }
                } else {
                    const float* hbase = ((l == 1) ? &sm->hs1[0][0] : &sm->hs2[1][0]) + (hf << 4);
                    const float* ibase = ((l == 1) ? &sm->hs0[0][0] : &sm->hs1[0][0]) + (hf << 4);
                    for (int r = rlo; r <= rhi; r++) {
                        u64 A0 = 0, A1 = 0, B0 = 0, B1 = 0;
                        const ulonglong2* hv =
                            reinterpret_cast<const ulonglong2*>(hbase + r * HH);
                        const ulonglong2* iv =
                            reinterpret_cast<const ulonglong2*>(ibase + r * HH);
#pragma unroll
                        for (int i = 0; i < 4; i++) {
                            FMA2(A0, wh[i].x, hv[i].x);
                            FMA2(A1, wh[i].y, hv[i].y);
                            FMA2(B0, wi[i].x, iv[i].x);
                            FMA2(B1, wi[i].y, iv[i].y);
                        }
                        float ph = sum2p(A0, A1);
                        float pi = sum2p(B0, B1);
                        pi += __shfl_xor_sync(0xffffffffu, pi, 16);
                        ph += __shfl_xor_sync(0xffffffffu, ph, 16);
                        if (hf == 0) {
                            float ah = ph + bias.y;
                            float ai = pi + bias.x;
                            int slot = r & 31;
                            if (isRZ) sm->rz[l][slot][g] = sigm_a(ai + ah);
                            else sm->n2[l][slot][g - 64] = make_float2(ai, ah);
                        }
                    }
                }
            }
            __syncthreads();

            // ---------- cell phase: 6 cells in flight (cell = rlo + w6, unit = lane) ----------
            if (act) {
                for (int r = rlo + w6; r <= rhi; r += 6) {
                    int slot = r & 31;
                    int t = m - 3 * r;
                    float rg = sm->rz[l][slot][lane];
                    float zg = sm->rz[l][slot][32 + lane];
                    float2 nn = sm->n2[l][slot][lane];
                    float ng = tanh_a(fmaf(rg, nn.y, nn.x));
                    float* hrow = (l == 0) ? &sm->hs0[r][0]
                                : (l == 1) ? &sm->hs1[r][0] : &sm->hs2[r + 1][0];
                    float hold = hrow[lane];
                    float hn = fmaf(zg, hold - ng, ng);
                    hrow[lane] = hn;
                    if (l == 2) hidG[(size_t)(r * CL + t) * HH + lane] = hn;
                }
            }
            issue_pout(s + 2);  // writes buf (s&1): all gate-phase reads of it are pre-barrier
            asm volatile("cp.async.commit_group;" ::: "memory");
            asm volatile("cp.async.wait_group 1;" ::: "memory");  // pout(s+1) landed
            __syncthreads();                                       // published for step s+1
        }
        __syncthreads();
    }
}

// ---------------- output projection with packed f32x2 FMA ----------------
__global__ void __launch_bounds__(256, 2) proj_kernel(const float* __restrict__ Wout,
                                                      const float* __restrict__ bout,
                                                      float* __restrict__ out) {
    __shared__ float Ws[32][264];  // Ws[k][v]
    __shared__ float hs[32][72];   // hs[k][p]
    __shared__ float bs[264];

    const int tid = threadIdx.x;
    const size_t p0 = (size_t)blockIdx.x * 64;

    for (int i = tid; i < VV * HH; i += 256) {
        int v = i >> 5, k = i & 31;
        Ws[k][v] = Wout[i];
    }
    if (tid < 256) bs[tid] = (tid < VV) ? bout[tid] : 0.f;
    if (tid < 2) bs[256 + tid] = bout[256 + tid];
    if (tid < 6) bs[258 + tid] = 0.f;
    {
        const float* hsrc = g_hid + p0 * HH;
        for (int i = tid; i < 64 * HH; i += 256) {
            int p = i >> 5, k = i & 31;
            hs[k][p] = hsrc[i];
        }
    }
    __syncthreads();

    const int tv = tid & 31;
    const int tp = tid >> 5;
    const int vb = tv * 8, pb = tp * 8;

    u64 acc[8][4];
#pragma unroll
    for (int pi = 0; pi < 8; pi++)
#pragma unroll
        for (int j = 0; j < 4; j++) acc[pi][j] = 0ull;

#pragma unroll 2
    for (int k = 0; k < 32; k++) {
        ulonglong2 w0 = *reinterpret_cast<const ulonglong2*>(&Ws[k][vb]);
        ulonglong2 w1 = *reinterpret_cast<const ulonglong2*>(&Ws[k][vb + 4]);
        float4 ha = *reinterpret_cast<const float4*>(&hs[k][pb]);
        float4 hb = *reinterpret_cast<const float4*>(&hs[k][pb + 4]);
        float hv[8] = {ha.x, ha.y, ha.z, ha.w, hb.x, hb.y, hb.z, hb.w};
#pragma unroll
        for (int pi = 0; pi < 8; pi++) {
            u64 hp;
            asm("mov.b64 %0, {%1, %1};" : "=l"(hp) : "f"(hv[pi]));
            FMA2(acc[pi][0], hp, w0.x);
            FMA2(acc[pi][1], hp, w0.y);
            FMA2(acc[pi][2], hp, w1.x);
            FMA2(acc[pi][3], hp, w1.y);
        }
    }

    ulonglong2 bz0 = *reinterpret_cast<const ulonglong2*>(&bs[vb]);
    ulonglong2 bz1 = *reinterpret_cast<const ulonglong2*>(&bs[vb + 4]);
    u64 bzv[4] = {bz0.x, bz0.y, bz1.x, bz1.y};

#pragma unroll
    for (int pi = 0; pi < 8; pi++) {
        size_t base = (p0 + pb + pi) * VV + vb;
#pragma unroll
        for (int j = 0; j < 4; j++) {
            u64 o;
            asm("add.rn.f32x2 %0, %1, %2;" : "=l"(o) : "l"(acc[pi][j]), "l"(bzv[j]));
            *reinterpret_cast<u64*>(&out[base + 2 * j]) = o;
        }
    }

    // tail columns v = 256, 257
    if (tid < 128) {
        int p = tid >> 1;
        int v = 256 + (tid & 1);
        float a = bs[v];
#pragma unroll
        for (int k = 0; k < 32; k++) a = fmaf(hs[k][p], Ws[k][v], a);
        out[(p0 + p) * VV + v] = a;
    }
}

// ---------------- launcher ----------------
extern "C" void kernel_launch(void* const* d_in, const int* in_sizes, int n_in,
                              void* d_out, int out_size) {
    const int* x = (const int*)d_in[0];
    const float* embed = (const float*)d_in[1];
    const float* Wih0 = (const float*)d_in[2];
    const float* Wih_rest = (const float*)d_in[3];
    const float* Whh = (const float*)d_in[4];
    const float* bih = (const float*)d_in[5];
    const float* bhh = (const float*)d_in[6];
    const float* W_h2e = (const float*)d_in[7];
    const float* b_h2e = (const float*)d_in[8];
    const float* W_ad = (const float*)d_in[9];
    const float* b_ad = (const float*)d_in[10];
    const float* W_out = (const float*)d_in[11];
    const float* b_out = (const float*)d_in[12];
    float* out = (float*)d_out;

    cudaFuncSetAttribute(rnn_kernel, cudaFuncAttributeMaxDynamicSharedMemorySize,
                         (int)sizeof(SmemT));

    prep_giemb<<<(CC * VV * GG + 127) / 128, 128>>>(Wih0, embed);
    prep_wpk3<<<(CC * 576 * 48 + 127) / 128, 128>>>(Wih0, Wih_rest, Whh, W_h2e, W_ad);
    prep_bpk3<<<(CC * 576 + 127) / 128, 128>>>(Wih0, bih, bhh, b_h2e, b_ad);
    rnn_kernel<<<BB, 576, sizeof(SmemT)>>>(x);
    proj_kernel<<<(BB * CC * RR * CL) / 64, 256>>>(W_out, b_out, out);
}

// round 13
// speedup vs baseline: 1.3282x; 1.3282x over previous
#include <cuda_runtime.h>

#define BB 64
#define CC 3
#define RR 64
#define CL 64
#define EE 64
#define HH 32
#define LL 3
#define VV 258
#define GG 96   // 3*H

typedef unsigned long long u64;

// ---------------- scratch (device globals; no allocation) ----------------
__device__ float g_giemb[CC * VV * GG];                   // [c][v][g] = Wih0[:, :64] @ embed
__device__ float g_wpk[CC * 288 * 96];                    // per-thread packed rows: wi[32], wh[32], wq[32]
__device__ float g_bpk[CC * 288 * 4];                     // per-thread bias: (bi, bh, pv, 0)
__device__ float g_hid[(size_t)BB * CC * RR * CL * HH];   // all hidden outputs (~100 MB)
__device__ float g_qpre[(size_t)CC * BB * RR * CL * GG];  // hoisted l0 input terms (~302 MB)

// ---------------- helpers ----------------
#define FMA2(acc, a, b) asm("fma.rn.f32x2 %0, %1, %2, %0;" : "+l"(acc) : "l"(a), "l"(b))

__device__ __forceinline__ float sum2p(u64 a, u64 b) {
    u64 s;
    asm("add.rn.f32x2 %0, %1, %2;" : "=l"(s) : "l"(a), "l"(b));
    float lo = __uint_as_float((unsigned)(s & 0xffffffffull));
    float hi = __uint_as_float((unsigned)(s >> 32));
    return lo + hi;
}
__device__ __forceinline__ void cpa16(void* dst, const void* src) {
    unsigned sd = (unsigned)__cvta_generic_to_shared(dst);
    asm volatile("cp.async.ca.shared.global [%0], [%1], 16;" :: "r"(sd), "l"(src) : "memory");
}
__device__ __forceinline__ float sigm_a(float x) {
    float t;
    asm("tanh.approx.f32 %0, %1;" : "=f"(t) : "f"(0.5f * x));
    return fmaf(0.5f, t, 0.5f);
}
__device__ __forceinline__ float tanh_a(float x) {
    float t;
    asm("tanh.approx.f32 %0, %1;" : "=f"(t) : "f"(x));
    return t;
}

// ---------------- dynamic shared layout ----------------
struct SmemT {
    float hs0[RR][HH];       // layer-0 hidden per row
    float hs1[RR][HH];       // layer-1 hidden per row
    float hs2[RR + 1][HH];   // layer-2 hidden per row, +1 offset; [0] = zeros (row -1)
    float rz[LL][32][64];    // finished sigma(r), sigma(z) per (layer, slot=r&31)
    float2 n2[LL][32][HH];   // (i_n, h_n) pairs
    float qx[2][32][GG];     // hoisted l0 input terms, double-buffered by step parity
};

// ---------------- precompute kernels (R11 layouts, proven) ----------------
__global__ void prep_giemb(const float* __restrict__ Wih0, const float* __restrict__ embed) {
    int idx = blockIdx.x * blockDim.x + threadIdx.x;
    if (idx >= CC * VV * GG) return;
    int c = idx / (VV * GG);
    int rem = idx % (VV * GG);
    int v = rem / GG;
    int g = rem % GG;
    const float* wr = Wih0 + (c * GG + g) * (EE + 1);
    const float* em = embed + (c * VV + v) * EE;
    float acc = 0.f;
#pragma unroll
    for (int e = 0; e < EE; e++) acc += wr[e] * em[e];
    g_giemb[idx] = acc;
}

// Per (c, thread t in [0,288)): l = t/96, g = t%96. 96 floats:
//   [0:32)  wi : l==0 -> Wfh[g] (Wih0 @ W_h2e); l>=1 -> Wih_rest[c][l-1][g]
//   [32:64) wh : Whh[c][l][g]
//   [64:96) wq : l==0 && c>0 -> Wfad[g] (Wih0 @ W_ad); else 0   (used by qpre kernel)
__global__ void prep_wpk2(const float* __restrict__ Wih0, const float* __restrict__ Wih_rest,
                          const float* __restrict__ Whh, const float* __restrict__ W_h2e,
                          const float* __restrict__ W_ad) {
    int idx = blockIdx.x * blockDim.x + threadIdx.x;
    if (idx >= CC * 288 * 96) return;
    int c = idx / (288 * 96);
    int rem = idx % (288 * 96);
    int t = rem / 96;
    int j = rem % 96;
    int s = j / 32;
    int k = j % 32;
    int l = t / 96;
    int g = t % 96;
    float val = 0.f;
    if (s == 0) {
        if (l == 0) {
            const float* wr = Wih0 + (c * GG + g) * (EE + 1);
            for (int e = 0; e <= EE; e++)
                val += wr[e] * W_h2e[(c * (EE + 1) + e) * HH + k];
        } else {
            val = Wih_rest[((c * (LL - 1) + (l - 1)) * GG + g) * HH + k];
        }
    } else if (s == 1) {
        val = Whh[((c * LL + l) * GG + g) * HH + k];
    } else {
        if (l == 0 && c > 0) {
            const float* wr = Wih0 + (c * GG + g) * (EE + 1);
            for (int e = 0; e <= EE; e++)
                val += wr[e] * W_ad[((c - 1) * (EE + 1) + e) * HH + k];
        }
    }
    g_wpk[idx] = val;
}

__global__ void prep_bpk2(const float* __restrict__ Wih0, const float* __restrict__ bih,
                          const float* __restrict__ bhh, const float* __restrict__ b_h2e,
                          const float* __restrict__ b_ad) {
    int idx = blockIdx.x * blockDim.x + threadIdx.x;
    if (idx >= CC * 288) return;
    int c = idx / 288;
    int t = idx % 288;
    int l = t / 96;
    int g = t % 96;
    float bi, bh, pv;
    if (l == 0) {
        bi = bih[(c * LL + 0) * GG + g];
        const float* wr = Wih0 + (c * GG + g) * (EE + 1);
        for (int e = 0; e <= EE; e++) {
            float bb = b_h2e[c * (EE + 1) + e];
            if (c > 0) bb += b_ad[(c - 1) * (EE + 1) + e];
            bi += wr[e] * bb;
        }
        pv = Wih0[(c * GG + g) * (EE + 1) + EE];
    } else {
        bi = bih[(c * LL + l) * GG + g];
        pv = 0.f;
    }
    bh = bhh[(c * LL + l) * GG + g];
    g_bpk[idx * 4 + 0] = bi;
    g_bpk[idx * 4 + 1] = bh;
    g_bpk[idx * 4 + 2] = pv;
    g_bpk[idx * 4 + 3] = 0.f;
}

// ---------------- qpre: full layer-0 input-side hoist (R8 kernel + bias fold) ----------------
// qpre[c][pos][g] = giemb[c][x[pos]][g] + (c>0 ? Wfad[c][g].hid[c-1][pos] : 0)
//                 + bih0[c][g] + pv[c][g]*pos_r
// pos = b*4096 + r*64 + t. Runs after rnn(c-1). grid = 8192, block = 96.
__global__ void __launch_bounds__(96, 8) qpre_kernel(int c, const int* __restrict__ x) {
    __shared__ __align__(16) float sh[32][32];
    __shared__ int sx[32];
    const int g = threadIdx.x;
    const size_t pos0 = (size_t)blockIdx.x * 32;
    const int b = (int)(pos0 >> 12);
    const int rt0 = (int)(pos0 & 4095);
    const int r = rt0 >> 6;  // 32 | 64, so r is constant within a block
    const float posr = (float)r * (1.f / 32.f) - 1.f;

    ulonglong2 wq[8];
    if (c > 0) {
        const ulonglong2* wsrc =
            reinterpret_cast<const ulonglong2*>(g_wpk + ((size_t)(c * 288 + g)) * 96 + 64);
#pragma unroll
        for (int i = 0; i < 8; i++) wq[i] = wsrc[i];
        const float4* hsrc = reinterpret_cast<const float4*>(
            g_hid + ((size_t)(b * CC + c - 1) * (RR * CL) + rt0) * HH);
        float4* shd = reinterpret_cast<float4*>(&sh[0][0]);
        for (int i = g; i < 256; i += 96) shd[i] = hsrc[i];
    }
    if (g < 32) sx[g] = x[((size_t)(b * CC + c) * (RR * CL)) + rt0 + g];
    __syncthreads();

    const float bi = g_bpk[(c * 288 + g) * 4 + 0];
    const float pv = g_bpk[(c * 288 + g) * 4 + 2];
    const float badd = fmaf(pv, posr, bi);

    const float* giC = g_giemb + (size_t)c * VV * GG;
    float* outp = g_qpre + ((size_t)c * (BB * RR * CL) + pos0) * GG + g;
#pragma unroll 4
    for (int p = 0; p < 32; p++) {
        float val = __ldg(giC + (size_t)sx[p] * GG + g) + badd;
        if (c > 0) {
            u64 A0 = 0, A1 = 0;
            const ulonglong2* hv = reinterpret_cast<const ulonglong2*>(&sh[p][0]);
#pragma unroll
            for (int i = 0; i < 8; i++) {
                FMA2(A0, wq[i].x, hv[i].x);
                FMA2(A1, wq[i].y, hv[i].y);
            }
            val += sum2p(A0, A1);
        }
        outp[(size_t)p * GG] = val;
    }
}

// ---------------- wavefront RNN kernel (one channel per launch) ----------------
// Schedule: layer l of cell (r,t) runs at step s = 3r + t + l (all deps one step old).
// All layer groups symmetric: per cell = 2 dots of 32 + activation. Layer-0's input-side
// terms arrive precomputed in qx via cp.async (issue s+2 -> commit -> wait 1 -> bar).
__global__ void __launch_bounds__(288, 1) rnn_kernel(int c) {
    extern __shared__ __align__(16) char smem_raw[];
    SmemT* sm = reinterpret_cast<SmemT*>(smem_raw);

    const int b = blockIdx.x;
    const int tid = threadIdx.x;
    const int l = tid / 96;   // layer group (warp-uniform)
    const int g = tid % 96;   // gate
    const int u = g & 31;     // cell-phase unit
    const int ci0 = g >> 5;   // cell-phase cell offset

    // per-thread packed weights (f32x2 pairs); wq unused here (hoisted into qpre)
    const ulonglong2* wv =
        reinterpret_cast<const ulonglong2*>(g_wpk + ((size_t)(c * 288 + tid)) * 96);
    ulonglong2 wi[8], wh[8];
#pragma unroll
    for (int i = 0; i < 8; i++) wi[i] = wv[i];
#pragma unroll
    for (int i = 0; i < 8; i++) wh[i] = wv[8 + i];
    const float4 bias = reinterpret_cast<const float4*>(g_bpk)[c * 288 + tid];

    const float* qpreC = g_qpre + ((size_t)c * BB + b) * (RR * CL) * GG;
    float* hidG = g_hid + (size_t)(b * CC + c) * (RR * CL * HH);

    // zero hidden states (hs0,hs1,hs2 contiguous)
    for (int i = tid; i < (RR + RR + RR + 1) * HH; i += 288) (&sm->hs0[0][0])[i] = 0.f;

    // qx prefetch: fill buf (m2&1) with qpre for layer-0 cells on line 3r+t = m2
    auto issue_qx = [&](int m2) {
        if (m2 > 252) return;
        int rlo2 = m2 > 61 ? (m2 - 61) / 3 : 0;
        int rhi2 = min(63, m2 / 3);
        int nch = (rhi2 - rlo2 + 1) * 24;  // 24 x 16B chunks per cell (96 floats)
        for (int id = tid; id < nch; id += 288) {
            int ce = id / 24, sub = id % 24;
            int r = rlo2 + ce, t = m2 - 3 * r;
            cpa16(&sm->qx[m2 & 1][r & 31][sub * 4],
                  qpreC + ((size_t)(r * CL + t) * GG + sub * 4));
        }
    };

    // prologue: qx(0), qx(1); publish before the loop
    issue_qx(0);
    asm volatile("cp.async.commit_group;" ::: "memory");
    issue_qx(1);
    asm volatile("cp.async.commit_group;" ::: "memory");
    asm volatile("cp.async.wait_group 1;" ::: "memory");  // qx(0) landed (this thread)
    __syncthreads();                                       // hs zero + qx(0) published

    for (int s = 0; s < 255; s++) {
        const int m = s - l;  // warp-uniform diagonal for this layer group
        const bool act = (m >= 0) && (m <= 252);
        int rlo = 0, rhi = -1;
        if (act) {
            rlo = m > 61 ? (m - 61) / 3 : 0;
            rhi = min(63, m / 3);
        }

        // ---------- gate phase ----------
        if (act) {
            if (l == 0) {
                const int buf = s & 1;
#pragma unroll 2
                for (int r = rlo; r <= rhi; r++) {
                    int slot = r & 31;
                    float qv = sm->qx[buf][slot][g];
                    u64 A0 = 0, A1 = 0, B0 = 0, B1 = 0;
                    const ulonglong2* hv = reinterpret_cast<const ulonglong2*>(&sm->hs0[r][0]);
                    const ulonglong2* iv = reinterpret_cast<const ulonglong2*>(&sm->hs2[r][0]);
#pragma unroll
                    for (int i = 0; i < 8; i++) {
                        FMA2(A0, wh[i].x, hv[i].x);
                        FMA2(A1, wh[i].y, hv[i].y);
                        FMA2(B0, wi[i].x, iv[i].x);
                        FMA2(B1, wi[i].y, iv[i].y);
                    }
                    float ah = sum2p(A0, A1) + bias.y;
                    float ai = sum2p(B0, B1) + qv;  // bi + pv*pos folded into qpre
                    if (g < 64) sm->rz[0][slot][g] = sigm_a(ai + ah);
                    else sm->n2[0][slot][g - 64] = make_float2(ai, ah);
                }
            } else {
                const float* hbase = (l == 1) ? &sm->hs1[0][0] : &sm->hs2[1][0];
                const float* ibase = (l == 1) ? &sm->hs0[0][0] : &sm->hs1[0][0];
#pragma unroll 2
                for (int r = rlo; r <= rhi; r++) {
                    u64 A0 = 0, A1 = 0, B0 = 0, B1 = 0;
                    const ulonglong2* hv = reinterpret_cast<const ulonglong2*>(hbase + r * HH);
                    const ulonglong2* iv = reinterpret_cast<const ulonglong2*>(ibase + r * HH);
#pragma unroll
                    for (int i = 0; i < 8; i++) {
                        FMA2(A0, wh[i].x, hv[i].x);
                        FMA2(A1, wh[i].y, hv[i].y);
                        FMA2(B0, wi[i].x, iv[i].x);
                        FMA2(B1, wi[i].y, iv[i].y);
                    }
                    float ah = sum2p(A0, A1) + bias.y;
                    float ai = sum2p(B0, B1) + bias.x;
                    int slot = r & 31;
                    if (g < 64) sm->rz[l][slot][g] = sigm_a(ai + ah);
                    else sm->n2[l][slot][g - 64] = make_float2(ai, ah);
                }
            }
        }
        __syncthreads();

        // ---------- cell phase (+ qx prefetch for s+2, post-read) ----------
        if (act) {
            for (int r = rlo + ci0; r <= rhi; r += 3) {
                int slot = r & 31;
                int t = m - 3 * r;
                float rg = sm->rz[l][slot][u];
                float zg = sm->rz[l][slot][32 + u];
                float2 nn = sm->n2[l][slot][u];
                float ng = tanh_a(fmaf(rg, nn.y, nn.x));
                float* hrow = (l == 0) ? &sm->hs0[r][0]
                            : (l == 1) ? &sm->hs1[r][0] : &sm->hs2[r + 1][0];
                float hold = hrow[u];
                float hn = fmaf(zg, hold - ng, ng);
                hrow[u] = hn;
                if (l == 2) hidG[(size_t)(r * CL + t) * HH + u] = hn;
            }
        }
        issue_qx(s + 2);  // writes buf (s&1): all gate-phase reads of it are pre-barrier
        asm volatile("cp.async.commit_group;" ::: "memory");
        asm volatile("cp.async.wait_group 1;" ::: "memory");  // qx(s+1) landed (this thread)
        __syncthreads();                                       // published for step s+1
    }
}

// ---------------- output projection with packed f32x2 FMA ----------------
__global__ void __launch_bounds__(256, 2) proj_kernel(const float* __restrict__ Wout,
                                                      const float* __restrict__ bout,
                                                      float* __restrict__ out) {
    __shared__ float Ws[32][264];  // Ws[k][v]
    __shared__ float hs[32][72];   // hs[k][p]
    __shared__ float bs[264];

    const int tid = threadIdx.x;
    const size_t p0 = (size_t)blockIdx.x * 64;

    for (int i = tid; i < VV * HH; i += 256) {
        int v = i >> 5, k = i & 31;
        Ws[k][v] = Wout[i];
    }
    if (tid < 256) bs[tid] = (tid < VV) ? bout[tid] : 0.f;
    if (tid < 2) bs[256 + tid] = bout[256 + tid];
    if (tid < 6) bs[258 + tid] = 0.f;
    {
        const float* hsrc = g_hid + p0 * HH;
        for (int i = tid; i < 64 * HH; i += 256) {
            int p = i >> 5, k = i & 31;
            hs[k][p] = hsrc[i];
        }
    }
    __syncthreads();

    const int tv = tid & 31;
    const int tp = tid >> 5;
    const int vb = tv * 8, pb = tp * 8;

    u64 acc[8][4];
#pragma unroll
    for (int pi = 0; pi < 8; pi++)
#pragma unroll
        for (int j = 0; j < 4; j++) acc[pi][j] = 0ull;

#pragma unroll 2
    for (int k = 0; k < 32; k++) {
        ulonglong2 w0 = *reinterpret_cast<const ulonglong2*>(&Ws[k][vb]);
        ulonglong2 w1 = *reinterpret_cast<const ulonglong2*>(&Ws[k][vb + 4]);
        float4 ha = *reinterpret_cast<const float4*>(&hs[k][pb]);
        float4 hb = *reinterpret_cast<const float4*>(&hs[k][pb + 4]);
        float hv[8] = {ha.x, ha.y, ha.z, ha.w, hb.x, hb.y, hb.z, hb.w};
#pragma unroll
        for (int pi = 0; pi < 8; pi++) {
            u64 hp;
            asm("mov.b64 %0, {%1, %1};" : "=l"(hp) : "f"(hv[pi]));
            FMA2(acc[pi][0], hp, w0.x);
            FMA2(acc[pi][1], hp, w0.y);
            FMA2(acc[pi][2], hp, w1.x);
            FMA2(acc[pi][3], hp, w1.y);
        }
    }

    ulonglong2 bz0 = *reinterpret_cast<const ulonglong2*>(&bs[vb]);
    ulonglong2 bz1 = *reinterpret_cast<const ulonglong2*>(&bs[vb + 4]);
    u64 bzv[4] = {bz0.x, bz0.y, bz1.x, bz1.y};

#pragma unroll
    for (int pi = 0; pi < 8; pi++) {
        size_t base = (p0 + pb + pi) * VV + vb;
#pragma unroll
        for (int j = 0; j < 4; j++) {
            u64 o;
            asm("add.rn.f32x2 %0, %1, %2;" : "=l"(o) : "l"(acc[pi][j]), "l"(bzv[j]));
            *reinterpret_cast<u64*>(&out[base + 2 * j]) = o;
        }
    }

    // tail columns v = 256, 257
    if (tid < 128) {
        int p = tid >> 1;
        int v = 256 + (tid & 1);
        float a = bs[v];
#pragma unroll
        for (int k = 0; k < 32; k++) a = fmaf(hs[k][p], Ws[k][v], a);
        out[(p0 + p) * VV + v] = a;
    }
}

// ---------------- launcher ----------------
extern "C" void kernel_launch(void* const* d_in, const int* in_sizes, int n_in,
                              void* d_out, int out_size) {
    const int* x = (const int*)d_in[0];
    const float* embed = (const float*)d_in[1];
    const float* Wih0 = (const float*)d_in[2];
    const float* Wih_rest = (const float*)d_in[3];
    const float* Whh = (const float*)d_in[4];
    const float* bih = (const float*)d_in[5];
    const float* bhh = (const float*)d_in[6];
    const float* W_h2e = (const float*)d_in[7];
    const float* b_h2e = (const float*)d_in[8];
    const float* W_ad = (const float*)d_in[9];
    const float* b_ad = (const float*)d_in[10];
    const float* W_out = (const float*)d_in[11];
    const float* b_out = (const float*)d_in[12];
    float* out = (float*)d_out;

    cudaFuncSetAttribute(rnn_kernel, cudaFuncAttributeMaxDynamicSharedMemorySize,
                         (int)sizeof(SmemT));

    prep_giemb<<<(CC * VV * GG + 127) / 128, 128>>>(Wih0, embed);
    prep_wpk2<<<(CC * 288 * 96 + 127) / 128, 128>>>(Wih0, Wih_rest, Whh, W_h2e, W_ad);
    prep_bpk2<<<(CC * 288 + 127) / 128, 128>>>(Wih0, bih, bhh, b_h2e, b_ad);

    for (int c = 0; c < CC; c++) {
        qpre_kernel<<<(BB * RR * CL) / 32, 96>>>(c, x);
        rnn_kernel<<<BB, 288, sizeof(SmemT)>>>(c);
    }
    proj_kernel<<<(BB * CC * RR * CL) / 64, 256>>>(W_out, b_out, out);
}

// round 14
// speedup vs baseline: 1.3683x; 1.0301x over previous
#include <cuda_runtime.h>

#define BB 64
#define CC 3
#define RR 64
#define CL 64
#define EE 64
#define HH 32
#define LL 3
#define VV 258
#define GG 96   // 3*H

typedef unsigned long long u64;

// ---------------- scratch (device globals; no allocation) ----------------
__device__ float g_giemb[CC * VV * GG];                   // [c][v][g] = Wih0[:, :64] @ embed
__device__ float g_wpk[CC * 288 * 96];                    // per-thread packed rows: wi[32], wh[32], wq[32]
__device__ float g_bpk[CC * 288 * 4];                     // per-thread bias: (bi, bh, pv, 0)
__device__ float g_hid[(size_t)BB * CC * RR * CL * HH];   // all hidden outputs (~100 MB)
__device__ float g_qpre[(size_t)CC * BB * RR * CL * GG];  // hoisted l0 input terms (~302 MB)

// ---------------- helpers ----------------
#define FMA2(acc, a, b) asm("fma.rn.f32x2 %0, %1, %2, %0;" : "+l"(acc) : "l"(a), "l"(b))

__device__ __forceinline__ float sum2p(u64 a, u64 b) {
    u64 s;
    asm("add.rn.f32x2 %0, %1, %2;" : "=l"(s) : "l"(a), "l"(b));
    float lo = __uint_as_float((unsigned)(s & 0xffffffffull));
    float hi = __uint_as_float((unsigned)(s >> 32));
    return lo + hi;
}
__device__ __forceinline__ void cpa16(void* dst, const void* src) {
    unsigned sd = (unsigned)__cvta_generic_to_shared(dst);
    asm volatile("cp.async.ca.shared.global [%0], [%1], 16;" :: "r"(sd), "l"(src) : "memory");
}
__device__ __forceinline__ float sigm_a(float x) {
    float t;
    asm("tanh.approx.f32 %0, %1;" : "=f"(t) : "f"(0.5f * x));
    return fmaf(0.5f, t, 0.5f);
}
__device__ __forceinline__ float tanh_a(float x) {
    float t;
    asm("tanh.approx.f32 %0, %1;" : "=f"(t) : "f"(x));
    return t;
}

// ---------------- dynamic shared layout ----------------
struct SmemT {
    float hs0[RR][HH];       // layer-0 hidden per row
    float hs1[RR][HH];       // layer-1 hidden per row
    float hs2[RR + 1][HH];   // layer-2 hidden per row, +1 offset; [0] = zeros (row -1)
    float rz[LL][32][64];    // finished sigma(r), sigma(z) per (layer, slot=r&31)
    float2 n2[LL][32][HH];   // (i_n, h_n) pairs
    float qx[2][32][GG];     // hoisted l0 input terms, double-buffered by step parity
};

// ---------------- precompute kernels (R13, proven) ----------------
__global__ void prep_giemb(const float* __restrict__ Wih0, const float* __restrict__ embed) {
    int idx = blockIdx.x * blockDim.x + threadIdx.x;
    if (idx >= CC * VV * GG) return;
    int c = idx / (VV * GG);
    int rem = idx % (VV * GG);
    int v = rem / GG;
    int g = rem % GG;
    const float* wr = Wih0 + (c * GG + g) * (EE + 1);
    const float* em = embed + (c * VV + v) * EE;
    float acc = 0.f;
#pragma unroll
    for (int e = 0; e < EE; e++) acc += wr[e] * em[e];
    g_giemb[idx] = acc;
}

// Per (c, thread t in [0,288)): l = t/96, g = t%96. 96 floats:
//   [0:32)  wi : l==0 -> Wfh[g] (Wih0 @ W_h2e); l>=1 -> Wih_rest[c][l-1][g]
//   [32:64) wh : Whh[c][l][g]
//   [64:96) wq : l==0 && c>0 -> Wfad[g] (Wih0 @ W_ad); else 0   (used by qpre kernel)
__global__ void prep_wpk2(const float* __restrict__ Wih0, const float* __restrict__ Wih_rest,
                          const float* __restrict__ Whh, const float* __restrict__ W_h2e,
                          const float* __restrict__ W_ad) {
    int idx = blockIdx.x * blockDim.x + threadIdx.x;
    if (idx >= CC * 288 * 96) return;
    int c = idx / (288 * 96);
    int rem = idx % (288 * 96);
    int t = rem / 96;
    int j = rem % 96;
    int s = j / 32;
    int k = j % 32;
    int l = t / 96;
    int g = t % 96;
    float val = 0.f;
    if (s == 0) {
        if (l == 0) {
            const float* wr = Wih0 + (c * GG + g) * (EE + 1);
            for (int e = 0; e <= EE; e++)
                val += wr[e] * W_h2e[(c * (EE + 1) + e) * HH + k];
        } else {
            val = Wih_rest[((c * (LL - 1) + (l - 1)) * GG + g) * HH + k];
        }
    } else if (s == 1) {
        val = Whh[((c * LL + l) * GG + g) * HH + k];
    } else {
        if (l == 0 && c > 0) {
            const float* wr = Wih0 + (c * GG + g) * (EE + 1);
            for (int e = 0; e <= EE; e++)
                val += wr[e] * W_ad[((c - 1) * (EE + 1) + e) * HH + k];
        }
    }
    g_wpk[idx] = val;
}

__global__ void prep_bpk2(const float* __restrict__ Wih0, const float* __restrict__ bih,
                          const float* __restrict__ bhh, const float* __restrict__ b_h2e,
                          const float* __restrict__ b_ad) {
    int idx = blockIdx.x * blockDim.x + threadIdx.x;
    if (idx >= CC * 288) return;
    int c = idx / 288;
    int t = idx % 288;
    int l = t / 96;
    int g = t % 96;
    float bi, bh, pv;
    if (l == 0) {
        bi = bih[(c * LL + 0) * GG + g];
        const float* wr = Wih0 + (c * GG + g) * (EE + 1);
        for (int e = 0; e <= EE; e++) {
            float bb = b_h2e[c * (EE + 1) + e];
            if (c > 0) bb += b_ad[(c - 1) * (EE + 1) + e];
            bi += wr[e] * bb;
        }
        pv = Wih0[(c * GG + g) * (EE + 1) + EE];
    } else {
        bi = bih[(c * LL + l) * GG + g];
        pv = 0.f;
    }
    bh = bhh[(c * LL + l) * GG + g];
    g_bpk[idx * 4 + 0] = bi;
    g_bpk[idx * 4 + 1] = bh;
    g_bpk[idx * 4 + 2] = pv;
    g_bpk[idx * 4 + 3] = 0.f;
}

// ---------------- qpre: full layer-0 input-side hoist (R13, proven) ----------------
// qpre[c][pos][g] = giemb[c][x[pos]][g] + (c>0 ? Wfad[c][g].hid[c-1][pos] : 0)
//                 + bih0[c][g] + pv[c][g]*pos_r
__global__ void __launch_bounds__(96, 8) qpre_kernel(int c, const int* __restrict__ x) {
    __shared__ __align__(16) float sh[32][32];
    __shared__ int sx[32];
    const int g = threadIdx.x;
    const size_t pos0 = (size_t)blockIdx.x * 32;
    const int b = (int)(pos0 >> 12);
    const int rt0 = (int)(pos0 & 4095);
    const int r = rt0 >> 6;
    const float posr = (float)r * (1.f / 32.f) - 1.f;

    ulonglong2 wq[8];
    if (c > 0) {
        const ulonglong2* wsrc =
            reinterpret_cast<const ulonglong2*>(g_wpk + ((size_t)(c * 288 + g)) * 96 + 64);
#pragma unroll
        for (int i = 0; i < 8; i++) wq[i] = wsrc[i];
        const float4* hsrc = reinterpret_cast<const float4*>(
            g_hid + ((size_t)(b * CC + c - 1) * (RR * CL) + rt0) * HH);
        float4* shd = reinterpret_cast<float4*>(&sh[0][0]);
        for (int i = g; i < 256; i += 96) shd[i] = hsrc[i];
    }
    if (g < 32) sx[g] = x[((size_t)(b * CC + c) * (RR * CL)) + rt0 + g];
    __syncthreads();

    const float bi = g_bpk[(c * 288 + g) * 4 + 0];
    const float pv = g_bpk[(c * 288 + g) * 4 + 2];
    const float badd = fmaf(pv, posr, bi);

    const float* giC = g_giemb + (size_t)c * VV * GG;
    float* outp = g_qpre + ((size_t)c * (BB * RR * CL) + pos0) * GG + g;
#pragma unroll 4
    for (int p = 0; p < 32; p++) {
        float val = __ldg(giC + (size_t)sx[p] * GG + g) + badd;
        if (c > 0) {
            u64 A0 = 0, A1 = 0;
            const ulonglong2* hv = reinterpret_cast<const ulonglong2*>(&sh[p][0]);
#pragma unroll
            for (int i = 0; i < 8; i++) {
                FMA2(A0, wq[i].x, hv[i].x);
                FMA2(A1, wq[i].y, hv[i].y);
            }
            val += sum2p(A0, A1);
        }
        outp[(size_t)p * GG] = val;
    }
}

// ---------------- wavefront RNN kernel (one channel per launch) ----------------
// Schedule: layer l of cell (r,t) runs at step s = 3r + t + l (all deps one step old).
// Gate phase processes diagonal cells in PAIRS with 8 independent accumulators so
// cell B's LDS overlaps cell A's FMA chain (manual software pipelining).
__global__ void __launch_bounds__(288, 1) rnn_kernel(int c) {
    extern __shared__ __align__(16) char smem_raw[];
    SmemT* sm = reinterpret_cast<SmemT*>(smem_raw);

    const int b = blockIdx.x;
    const int tid = threadIdx.x;
    const int l = tid / 96;   // layer group (warp-uniform)
    const int g = tid % 96;   // gate
    const int u = g & 31;     // cell-phase unit
    const int ci0 = g >> 5;   // cell-phase cell offset

    const ulonglong2* wv =
        reinterpret_cast<const ulonglong2*>(g_wpk + ((size_t)(c * 288 + tid)) * 96);
    ulonglong2 wi[8], wh[8];
#pragma unroll
    for (int i = 0; i < 8; i++) wi[i] = wv[i];
#pragma unroll
    for (int i = 0; i < 8; i++) wh[i] = wv[8 + i];
    const float4 bias = reinterpret_cast<const float4*>(g_bpk)[c * 288 + tid];

    const float* qpreC = g_qpre + ((size_t)c * BB + b) * (RR * CL) * GG;
    float* hidG = g_hid + (size_t)(b * CC + c) * (RR * CL * HH);

    // zero hidden states (hs0,hs1,hs2 contiguous)
    for (int i = tid; i < (RR + RR + RR + 1) * HH; i += 288) (&sm->hs0[0][0])[i] = 0.f;

    // qx prefetch: fill buf (m2&1) with qpre for layer-0 cells on line 3r+t = m2
    auto issue_qx = [&](int m2) {
        if (m2 > 252) return;
        int rlo2 = m2 > 61 ? (m2 - 61) / 3 : 0;
        int rhi2 = min(63, m2 / 3);
        int nch = (rhi2 - rlo2 + 1) * 24;  // 24 x 16B chunks per cell (96 floats)
        for (int id = tid; id < nch; id += 288) {
            int ce = id / 24, sub = id % 24;
            int r = rlo2 + ce, t = m2 - 3 * r;
            cpa16(&sm->qx[m2 & 1][r & 31][sub * 4],
                  qpreC + ((size_t)(r * CL + t) * GG + sub * 4));
        }
    };

    issue_qx(0);
    asm volatile("cp.async.commit_group;" ::: "memory");
    issue_qx(1);
    asm volatile("cp.async.commit_group;" ::: "memory");
    asm volatile("cp.async.wait_group 1;" ::: "memory");
    __syncthreads();

    for (int s = 0; s < 255; s++) {
        const int m = s - l;  // warp-uniform diagonal for this layer group
        const bool act = (m >= 0) && (m <= 252);
        int rlo = 0, rhi = -1;
        if (act) {
            rlo = m > 61 ? (m - 61) / 3 : 0;
            rhi = min(63, m / 3);
        }

        // ---------- gate phase: paired cells, 8 accumulators ----------
        if (act) {
            const float* hbase = (l == 0) ? &sm->hs0[0][0]
                               : (l == 1) ? &sm->hs1[0][0] : &sm->hs2[1][0];
            const float* ibase = (l == 0) ? &sm->hs2[0][0]
                               : (l == 1) ? &sm->hs0[0][0] : &sm->hs1[0][0];
            const int buf = s & 1;
            int r = rlo;
            for (; r + 1 <= rhi; r += 2) {
                const int sa = r & 31, sb = (r + 1) & 31;
                float qa, qb;
                if (l == 0) {
                    qa = sm->qx[buf][sa][g];
                    qb = sm->qx[buf][sb][g];
                } else {
                    qa = bias.x;
                    qb = bias.x;
                }
                u64 A0a = 0, A1a = 0, B0a = 0, B1a = 0;
                u64 A0b = 0, A1b = 0, B0b = 0, B1b = 0;
                const ulonglong2* hva = reinterpret_cast<const ulonglong2*>(hbase + r * HH);
                const ulonglong2* iva = reinterpret_cast<const ulonglong2*>(ibase + r * HH);
                const ulonglong2* hvb = reinterpret_cast<const ulonglong2*>(hbase + (r + 1) * HH);
                const ulonglong2* ivb = reinterpret_cast<const ulonglong2*>(ibase + (r + 1) * HH);
#pragma unroll
                for (int i = 0; i < 8; i++) {
                    ulonglong2 xa = hva[i], ya = iva[i];
                    ulonglong2 xb = hvb[i], yb = ivb[i];
                    FMA2(A0a, wh[i].x, xa.x);
                    FMA2(A1a, wh[i].y, xa.y);
                    FMA2(B0a, wi[i].x, ya.x);
                    FMA2(B1a, wi[i].y, ya.y);
                    FMA2(A0b, wh[i].x, xb.x);
                    FMA2(A1b, wh[i].y, xb.y);
                    FMA2(B0b, wi[i].x, yb.x);
                    FMA2(B1b, wi[i].y, yb.y);
                }
                float aha = sum2p(A0a, A1a) + bias.y;
                float aia = sum2p(B0a, B1a) + qa;
                float ahb = sum2p(A0b, A1b) + bias.y;
                float aib = sum2p(B0b, B1b) + qb;
                if (g < 64) {
                    sm->rz[l][sa][g] = sigm_a(aia + aha);
                    sm->rz[l][sb][g] = sigm_a(aib + ahb);
                } else {
                    sm->n2[l][sa][g - 64] = make_float2(aia, aha);
                    sm->n2[l][sb][g - 64] = make_float2(aib, ahb);
                }
            }
            if (r <= rhi) {  // odd remainder cell
                const int sa = r & 31;
                float qa = (l == 0) ? sm->qx[buf][sa][g] : bias.x;
                u64 A0 = 0, A1 = 0, B0 = 0, B1 = 0;
                const ulonglong2* hv = reinterpret_cast<const ulonglong2*>(hbase + r * HH);
                const ulonglong2* iv = reinterpret_cast<const ulonglong2*>(ibase + r * HH);
#pragma unroll
                for (int i = 0; i < 8; i++) {
                    ulonglong2 xa = hv[i], ya = iv[i];
                    FMA2(A0, wh[i].x, xa.x);
                    FMA2(A1, wh[i].y, xa.y);
                    FMA2(B0, wi[i].x, ya.x);
                    FMA2(B1, wi[i].y, ya.y);
                }
                float ah = sum2p(A0, A1) + bias.y;
                float ai = sum2p(B0, B1) + qa;
                if (g < 64) sm->rz[l][sa][g] = sigm_a(ai + ah);
                else sm->n2[l][sa][g - 64] = make_float2(ai, ah);
            }
        }
        __syncthreads();

        // ---------- cell phase (+ qx prefetch for s+2, post-read) ----------
        if (act) {
#pragma unroll 2
            for (int r = rlo + ci0; r <= rhi; r += 3) {
                int slot = r & 31;
                int t = m - 3 * r;
                float rg = sm->rz[l][slot][u];
                float zg = sm->rz[l][slot][32 + u];
                float2 nn = sm->n2[l][slot][u];
                float ng = tanh_a(fmaf(rg, nn.y, nn.x));
                float* hrow = (l == 0) ? &sm->hs0[r][0]
                            : (l == 1) ? &sm->hs1[r][0] : &sm->hs2[r + 1][0];
                float hold = hrow[u];
                float hn = fmaf(zg, hold - ng, ng);
                hrow[u] = hn;
                if (l == 2) hidG[(size_t)(r * CL + t) * HH + u] = hn;
            }
        }
        issue_qx(s + 2);  // writes buf (s&1): all gate-phase reads of it are pre-barrier
        asm volatile("cp.async.commit_group;" ::: "memory");
        asm volatile("cp.async.wait_group 1;" ::: "memory");  // qx(s+1) landed (this thread)
        __syncthreads();                                       // published for step s+1
    }
}

// ---------------- output projection with packed f32x2 FMA ----------------
__global__ void __launch_bounds__(256, 2) proj_kernel(const float* __restrict__ Wout,
                                                      const float* __restrict__ bout,
                                                      float* __restrict__ out) {
    __shared__ float Ws[32][264];  // Ws[k][v]
    __shared__ float hs[32][72];   // hs[k][p]
    __shared__ float bs[264];

    const int tid = threadIdx.x;
    const size_t p0 = (size_t)blockIdx.x * 64;

    for (int i = tid; i < VV * HH; i += 256) {
        int v = i >> 5, k = i & 31;
        Ws[k][v] = Wout[i];
    }
    if (tid < 256) bs[tid] = (tid < VV) ? bout[tid] : 0.f;
    if (tid < 2) bs[256 + tid] = bout[256 + tid];
    if (tid < 6) bs[258 + tid] = 0.f;
    {
        const float* hsrc = g_hid + p0 * HH;
        for (int i = tid; i < 64 * HH; i += 256) {
            int p = i >> 5, k = i & 31;
            hs[k][p] = hsrc[i];
        }
    }
    __syncthreads();

    const int tv = tid & 31;
    const int tp = tid >> 5;
    const int vb = tv * 8, pb = tp * 8;

    u64 acc[8][4];
#pragma unroll
    for (int pi = 0; pi < 8; pi++)
#pragma unroll
        for (int j = 0; j < 4; j++) acc[pi][j] = 0ull;

#pragma unroll 2
    for (int k = 0; k < 32; k++) {
        ulonglong2 w0 = *reinterpret_cast<const ulonglong2*>(&Ws[k][vb]);
        ulonglong2 w1 = *reinterpret_cast<const ulonglong2*>(&Ws[k][vb + 4]);
        float4 ha = *reinterpret_cast<const float4*>(&hs[k][pb]);
        float4 hb = *reinterpret_cast<const float4*>(&hs[k][pb + 4]);
        float hv[8] = {ha.x, ha.y, ha.z, ha.w, hb.x, hb.y, hb.z, hb.w};
#pragma unroll
        for (int pi = 0; pi < 8; pi++) {
            u64 hp;
            asm("mov.b64 %0, {%1, %1};" : "=l"(hp) : "f"(hv[pi]));
            FMA2(acc[pi][0], hp, w0.x);
            FMA2(acc[pi][1], hp, w0.y);
            FMA2(acc[pi][2], hp, w1.x);
            FMA2(acc[pi][3], hp, w1.y);
        }
    }

    ulonglong2 bz0 = *reinterpret_cast<const ulonglong2*>(&bs[vb]);
    ulonglong2 bz1 = *reinterpret_cast<const ulonglong2*>(&bs[vb + 4]);
    u64 bzv[4] = {bz0.x, bz0.y, bz1.x, bz1.y};

#pragma unroll
    for (int pi = 0; pi < 8; pi++) {
        size_t base = (p0 + pb + pi) * VV + vb;
#pragma unroll
        for (int j = 0; j < 4; j++) {
            u64 o;
            asm("add.rn.f32x2 %0, %1, %2;" : "=l"(o) : "l"(acc[pi][j]), "l"(bzv[j]));
            *reinterpret_cast<u64*>(&out[base + 2 * j]) = o;
        }
    }

    // tail columns v = 256, 257
    if (tid < 128) {
        int p = tid >> 1;
        int v = 256 + (tid & 1);
        float a = bs[v];
#pragma unroll
        for (int k = 0; k < 32; k++) a = fmaf(hs[k][p], Ws[k][v], a);
        out[(p0 + p) * VV + v] = a;
    }
}

// ---------------- launcher ----------------
extern "C" void kernel_launch(void* const* d_in, const int* in_sizes, int n_in,
                              void* d_out, int out_size) {
    const int* x = (const int*)d_in[0];
    const float* embed = (const float*)d_in[1];
    const float* Wih0 = (const float*)d_in[2];
    const float* Wih_rest = (const float*)d_in[3];
    const float* Whh = (const float*)d_in[4];
    const float* bih = (const float*)d_in[5];
    const float* bhh = (const float*)d_in[6];
    const float* W_h2e = (const float*)d_in[7];
    const float* b_h2e = (const float*)d_in[8];
    const float* W_ad = (const float*)d_in[9];
    const float* b_ad = (const float*)d_in[10];
    const float* W_out = (const float*)d_in[11];
    const float* b_out = (const float*)d_in[12];
    float* out = (float*)d_out;

    cudaFuncSetAttribute(rnn_kernel, cudaFuncAttributeMaxDynamicSharedMemorySize,
                         (int)sizeof(SmemT));

    prep_giemb<<<(CC * VV * GG + 127) / 128, 128>>>(Wih0, embed);
    prep_wpk2<<<(CC * 288 * 96 + 127) / 128, 128>>>(Wih0, Wih_rest, Whh, W_h2e, W_ad);
    prep_bpk2<<<(CC * 288 + 127) / 128, 128>>>(Wih0, bih, bhh, b_h2e, b_ad);

    for (int c = 0; c < CC; c++) {
        qpre_kernel<<<(BB * RR * CL) / 32, 96>>>(c, x);
        rnn_kernel<<<BB, 288, sizeof(SmemT)>>>(c);
    }
    proj_kernel<<<(BB * CC * RR * CL) / 64, 256>>>(W_out, b_out, out);
}